// round 1
// baseline (speedup 1.0000x reference)
#include <cuda_runtime.h>

// ---------------------------------------------------------------------------
// SABlock: causal multi-head self-attention block, fp32.
//   B=4, T=2048, C=1024, H=16, D=64
//   q/k/v = x @ W{q,k,v}^T ; flash-attention (causal) ; out = y @ Wo^T + bo
// Round 0: fp32 FMA baseline. 3 launches. Scratch in __device__ globals.
// ---------------------------------------------------------------------------

#define BB 4
#define TT 2048
#define CC 1024
#define HH 16
#define DD 64
#define MM (BB * TT)        // 8192 rows

// Scratch (static device globals — allocation-free per harness rules)
__device__ __align__(16) float g_Q[BB * HH * TT * DD];
__device__ __align__(16) float g_K[BB * HH * TT * DD];
__device__ __align__(16) float g_V[BB * HH * TT * DD];
__device__ __align__(16) float g_Y[BB * TT * CC];

// ---------------------------------------------------------------------------
// Shared GEMM core: y[m,n] = sum_k A[m,k] * W[n,k]
// Block tile 128x128, K-step 8, 256 threads, 8x8 per-thread microtile.
// ---------------------------------------------------------------------------
__device__ __forceinline__ void gemm128(const float* __restrict__ A,
                                        const float* __restrict__ Wt,
                                        int m0, int n0, float acc[8][8])
{
    __shared__ float As[8][128];
    __shared__ float Bs[8][128];

    const int tid  = threadIdx.x;
    const int lrow = tid >> 1;          // 0..127
    const int lcol = (tid & 1) * 4;     // 0 or 4
    const float* Aptr = A  + (size_t)(m0 + lrow) * CC + lcol;
    const float* Bptr = Wt + (size_t)(n0 + lrow) * CC + lcol;
    const int rm = (tid >> 4) * 8;      // micro row base
    const int cn = (tid & 15) * 8;      // micro col base

    float4 ra = *(const float4*)(Aptr);
    float4 rb = *(const float4*)(Bptr);

    for (int kt = 0; kt < CC / 8; kt++) {
        __syncthreads();
        As[lcol + 0][lrow] = ra.x; As[lcol + 1][lrow] = ra.y;
        As[lcol + 2][lrow] = ra.z; As[lcol + 3][lrow] = ra.w;
        Bs[lcol + 0][lrow] = rb.x; Bs[lcol + 1][lrow] = rb.y;
        Bs[lcol + 2][lrow] = rb.z; Bs[lcol + 3][lrow] = rb.w;
        __syncthreads();
        if (kt + 1 < CC / 8) {
            ra = *(const float4*)(Aptr + (kt + 1) * 8);
            rb = *(const float4*)(Bptr + (kt + 1) * 8);
        }
        #pragma unroll
        for (int k = 0; k < 8; k++) {
            float4 a0 = *(const float4*)&As[k][rm];
            float4 a1 = *(const float4*)&As[k][rm + 4];
            float4 b0 = *(const float4*)&Bs[k][cn];
            float4 b1 = *(const float4*)&Bs[k][cn + 4];
            float av[8] = {a0.x, a0.y, a0.z, a0.w, a1.x, a1.y, a1.z, a1.w};
            float bv[8] = {b0.x, b0.y, b0.z, b0.w, b1.x, b1.y, b1.z, b1.w};
            #pragma unroll
            for (int i = 0; i < 8; i++)
                #pragma unroll
                for (int j = 0; j < 8; j++)
                    acc[i][j] = fmaf(av[i], bv[j], acc[i][j]);
        }
    }
}

// ---------------------------------------------------------------------------
// Kernel 1: fused QKV projection. grid = (N/128=8, M/128=64, 3)
// Epilogue scatters into [B,H,T,D].
// ---------------------------------------------------------------------------
__global__ void __launch_bounds__(256) qkv_kernel(const float* __restrict__ x,
                                                  const float* __restrict__ Wq,
                                                  const float* __restrict__ Wk,
                                                  const float* __restrict__ Wv)
{
    const int z = blockIdx.z;
    const float* W = (z == 0) ? Wq : (z == 1) ? Wk : Wv;
    float* dst     = (z == 0) ? g_Q : (z == 1) ? g_K : g_V;

    const int m0 = blockIdx.y * 128;
    const int n0 = blockIdx.x * 128;

    float acc[8][8];
    #pragma unroll
    for (int i = 0; i < 8; i++)
        #pragma unroll
        for (int j = 0; j < 8; j++) acc[i][j] = 0.f;

    gemm128(x, W, m0, n0, acc);

    const int tid = threadIdx.x;
    const int rm = (tid >> 4) * 8;
    const int cn = (tid & 15) * 8;
    #pragma unroll
    for (int i = 0; i < 8; i++) {
        const int m = m0 + rm + i;
        const int b = m >> 11;          // /T
        const int t = m & (TT - 1);
        #pragma unroll
        for (int jb = 0; jb < 8; jb += 4) {
            const int n = n0 + cn + jb;
            const int h = n >> 6;       // /D
            const int d = n & (DD - 1);
            float4 v = make_float4(acc[i][jb], acc[i][jb + 1], acc[i][jb + 2], acc[i][jb + 3]);
            *(float4*)&dst[((size_t)(b * HH + h) * TT + t) * DD + d] = v;
        }
    }
}

// ---------------------------------------------------------------------------
// Fast exp2 via FMA polynomial (avoids MUFU bottleneck: 134M exps total).
// Valid for t <= ~0.6 (we only call with t <= 0). Max rel err ~2.4e-6.
// ---------------------------------------------------------------------------
__device__ __forceinline__ float fexp2(float t)
{
    t = fmaxf(t, -126.0f);
    float r = t + 12582912.0f;                       // round-to-nearest int
    int   n = __float_as_int(r) - 0x4B400000;        // integer part
    float x = t - (r - 12582912.0f);                 // frac in [-0.5, 0.5]
    float p = 1.33335581e-3f;
    p = fmaf(p, x, 9.61812910e-3f);
    p = fmaf(p, x, 5.55041087e-2f);
    p = fmaf(p, x, 2.40226507e-1f);
    p = fmaf(p, x, 6.93147182e-1f);
    p = fmaf(p, x, 1.0f);
    return p * __int_as_float((n + 127) << 23);
}

// ---------------------------------------------------------------------------
// Kernel 2: causal flash attention. grid = (T/64 = 32 q-tiles, B*H = 64).
// 64x64 q/k tiles, online softmax, O accumulator in registers.
// ---------------------------------------------------------------------------
#define PADW 68
#define SMEM_ATTN_FLOATS (4 * 64 * PADW + 2 * 64 * 17 + 3 * 64)
#define SMEM_ATTN_BYTES  (SMEM_ATTN_FLOATS * 4)

__global__ void __launch_bounds__(256) attn_kernel()
{
    extern __shared__ float sm[];
    float* Qs   = sm;                   // 64 x PADW (pre-scaled)
    float* Ks   = Qs + 64 * PADW;
    float* Vs   = Ks + 64 * PADW;
    float* Ps   = Vs + 64 * PADW;
    float* pmax = Ps + 64 * PADW;       // 64 x 17
    float* psum = pmax + 64 * 17;       // 64 x 17
    float* mrow = psum + 64 * 17;       // 64
    float* lrow = mrow + 64;            // 64
    float* frow = lrow + 64;            // 64

    const int tid = threadIdx.x;
    const int bh  = blockIdx.y;
    const int qi  = gridDim.x - 1 - blockIdx.x;   // big tiles launched first
    const int t0  = qi * 64;
    const float scale = 0.125f;                   // 1/sqrt(64)
    const float LOG2E = 1.4426950408889634f;

    const float* Qg = g_Q + (size_t)bh * TT * DD;
    const float* Kg = g_K + (size_t)bh * TT * DD;
    const float* Vg = g_V + (size_t)bh * TT * DD;

    // Load Q tile (scaled)
    #pragma unroll
    for (int rep = 0; rep < 4; rep++) {
        int lin = rep * 1024 + tid * 4;
        int r = lin >> 6, c = lin & 63;
        float4 v = *(const float4*)&Qg[(size_t)(t0 + r) * DD + c];
        v.x *= scale; v.y *= scale; v.z *= scale; v.w *= scale;
        *(float4*)&Qs[r * PADW + c] = v;
    }
    if (tid < 64) { mrow[tid] = -1e30f; lrow[tid] = 0.f; }

    float o[16];
    #pragma unroll
    for (int i = 0; i < 16; i++) o[i] = 0.f;

    const int tr = tid >> 4, tc = tid & 15;       // S-phase 16x16 thread grid
    const int orow = tid >> 2, cb = (tid & 3) * 16; // PV-phase mapping

    for (int j = 0; j <= qi; j++) {
        __syncthreads();   // prior PV done before overwriting K/V/P
        // Load K and V tiles
        #pragma unroll
        for (int rep = 0; rep < 4; rep++) {
            int lin = rep * 1024 + tid * 4;
            int r = lin >> 6, c = lin & 63;
            *(float4*)&Ks[r * PADW + c] = *(const float4*)&Kg[(size_t)(j * 64 + r) * DD + c];
            *(float4*)&Vs[r * PADW + c] = *(const float4*)&Vg[(size_t)(j * 64 + r) * DD + c];
        }
        __syncthreads();

        // --- S = Qs * Ks^T  (4x4 microtile per thread) ---
        float s[4][4];
        #pragma unroll
        for (int i = 0; i < 4; i++)
            #pragma unroll
            for (int jj = 0; jj < 4; jj++) s[i][jj] = 0.f;

        #pragma unroll 4
        for (int d4 = 0; d4 < 64; d4 += 4) {
            float4 q[4], k[4];
            #pragma unroll
            for (int i = 0; i < 4; i++)
                q[i] = *(const float4*)&Qs[(tr * 4 + i) * PADW + d4];
            #pragma unroll
            for (int jj = 0; jj < 4; jj++)
                k[jj] = *(const float4*)&Ks[(tc * 4 + jj) * PADW + d4];
            #pragma unroll
            for (int i = 0; i < 4; i++)
                #pragma unroll
                for (int jj = 0; jj < 4; jj++) {
                    float acc = s[i][jj];
                    acc = fmaf(q[i].x, k[jj].x, acc);
                    acc = fmaf(q[i].y, k[jj].y, acc);
                    acc = fmaf(q[i].z, k[jj].z, acc);
                    acc = fmaf(q[i].w, k[jj].w, acc);
                    s[i][jj] = acc;
                }
        }
        // causal mask (only the diagonal tile)
        if (j == qi) {
            #pragma unroll
            for (int i = 0; i < 4; i++)
                #pragma unroll
                for (int jj = 0; jj < 4; jj++)
                    if (tc * 4 + jj > tr * 4 + i) s[i][jj] = -1e30f;
        }
        // partial row max
        #pragma unroll
        for (int i = 0; i < 4; i++) {
            float mx = fmaxf(fmaxf(s[i][0], s[i][1]), fmaxf(s[i][2], s[i][3]));
            pmax[(tr * 4 + i) * 17 + tc] = mx;
        }
        __syncthreads();
        if (tid < 64) {
            float mx = pmax[tid * 17];
            #pragma unroll
            for (int t = 1; t < 16; t++) mx = fmaxf(mx, pmax[tid * 17 + t]);
            float mo = mrow[tid];
            float mn = fmaxf(mo, mx);
            mrow[tid] = mn;
            frow[tid] = fexp2((mo - mn) * LOG2E);
        }
        __syncthreads();
        // exponentiate, write P, partial row sums
        #pragma unroll
        for (int i = 0; i < 4; i++) {
            float mn = mrow[tr * 4 + i];
            float rs = 0.f;
            float4 pv;
            pv.x = fexp2((s[i][0] - mn) * LOG2E);
            pv.y = fexp2((s[i][1] - mn) * LOG2E);
            pv.z = fexp2((s[i][2] - mn) * LOG2E);
            pv.w = fexp2((s[i][3] - mn) * LOG2E);
            rs = pv.x + pv.y + pv.z + pv.w;
            *(float4*)&Ps[(tr * 4 + i) * PADW + tc * 4] = pv;
            psum[(tr * 4 + i) * 17 + tc] = rs;
        }
        __syncthreads();
        if (tid < 64) {
            float rs = 0.f;
            #pragma unroll
            for (int t = 0; t < 16; t++) rs += psum[tid * 17 + t];
            lrow[tid] = lrow[tid] * frow[tid] + rs;
        }
        // --- rescale accumulator and O += P * V ---
        float f = frow[orow];
        #pragma unroll
        for (int i = 0; i < 16; i++) o[i] *= f;

        #pragma unroll 8
        for (int kk = 0; kk < 64; kk++) {
            float p = Ps[orow * PADW + kk];
            float4 v0 = *(const float4*)&Vs[kk * PADW + cb];
            float4 v1 = *(const float4*)&Vs[kk * PADW + cb + 4];
            float4 v2 = *(const float4*)&Vs[kk * PADW + cb + 8];
            float4 v3 = *(const float4*)&Vs[kk * PADW + cb + 12];
            o[0]  = fmaf(p, v0.x, o[0]);  o[1]  = fmaf(p, v0.y, o[1]);
            o[2]  = fmaf(p, v0.z, o[2]);  o[3]  = fmaf(p, v0.w, o[3]);
            o[4]  = fmaf(p, v1.x, o[4]);  o[5]  = fmaf(p, v1.y, o[5]);
            o[6]  = fmaf(p, v1.z, o[6]);  o[7]  = fmaf(p, v1.w, o[7]);
            o[8]  = fmaf(p, v2.x, o[8]);  o[9]  = fmaf(p, v2.y, o[9]);
            o[10] = fmaf(p, v2.z, o[10]); o[11] = fmaf(p, v2.w, o[11]);
            o[12] = fmaf(p, v3.x, o[12]); o[13] = fmaf(p, v3.y, o[13]);
            o[14] = fmaf(p, v3.z, o[14]); o[15] = fmaf(p, v3.w, o[15]);
        }
    }
    __syncthreads();   // lrow final values visible to all

    // epilogue: normalize, merge heads into g_Y [B,T,C]
    const float linv = 1.0f / lrow[orow];
    const int b = bh >> 4, h = bh & 15;
    float* yrow = g_Y + ((size_t)(b * TT + t0 + orow)) * CC + h * 64 + cb;
    #pragma unroll
    for (int g = 0; g < 4; g++) {
        float4 w = make_float4(o[g * 4] * linv, o[g * 4 + 1] * linv,
                               o[g * 4 + 2] * linv, o[g * 4 + 3] * linv);
        *(float4*)&yrow[g * 4] = w;
    }
}

// ---------------------------------------------------------------------------
// Kernel 3: output projection  out = Y @ Wo^T + bo.  grid = (8, 64)
// ---------------------------------------------------------------------------
__global__ void __launch_bounds__(256) outproj_kernel(const float* __restrict__ Wo,
                                                      const float* __restrict__ bo,
                                                      float* __restrict__ out)
{
    const int m0 = blockIdx.y * 128;
    const int n0 = blockIdx.x * 128;

    float acc[8][8];
    #pragma unroll
    for (int i = 0; i < 8; i++)
        #pragma unroll
        for (int j = 0; j < 8; j++) acc[i][j] = 0.f;

    gemm128(g_Y, Wo, m0, n0, acc);

    const int tid = threadIdx.x;
    const int rm = (tid >> 4) * 8;
    const int cn = (tid & 15) * 8;
    #pragma unroll
    for (int i = 0; i < 8; i++) {
        const int m = m0 + rm + i;
        #pragma unroll
        for (int jb = 0; jb < 8; jb += 4) {
            const int n = n0 + cn + jb;
            float4 bias = *(const float4*)&bo[n];
            float4 v = make_float4(acc[i][jb] + bias.x, acc[i][jb + 1] + bias.y,
                                   acc[i][jb + 2] + bias.z, acc[i][jb + 3] + bias.w);
            *(float4*)&out[(size_t)m * CC + n] = v;
        }
    }
}

// ---------------------------------------------------------------------------
// Launch
// ---------------------------------------------------------------------------
extern "C" void kernel_launch(void* const* d_in, const int* in_sizes, int n_in,
                              void* d_out, int out_size)
{
    const float* x  = (const float*)d_in[0];
    const float* Wq = (const float*)d_in[1];
    const float* Wk = (const float*)d_in[2];
    const float* Wv = (const float*)d_in[3];
    const float* Wo = (const float*)d_in[4];
    const float* bo = (const float*)d_in[5];
    float* out = (float*)d_out;

    cudaFuncSetAttribute(attn_kernel, cudaFuncAttributeMaxDynamicSharedMemorySize,
                         SMEM_ATTN_BYTES);

    qkv_kernel<<<dim3(8, 64, 3), 256>>>(x, Wq, Wk, Wv);
    attn_kernel<<<dim3(32, 64), 256, SMEM_ATTN_BYTES>>>();
    outproj_kernel<<<dim3(8, 64), 256>>>(Wo, bo, out);
}